// round 16
// baseline (speedup 1.0000x reference)
#include <cuda_runtime.h>
#include <cuda_bf16.h>
#include <math_constants.h>

#define D 8
#define K 8
#define TRI 36
#define PHI_DIM 360
#define M_MODELS 32
#define N_POINTS 32768
#define MT 128            // A rows per CTA (16 comps = 2 models)
#define NTL 128           // points per CTA
#define NTILES 256        // 32768 / 128
#define MBLOCKS 16        // 2048 / 128
#define SA 40             // bf16 row stride for A/B smem+global ([hi16|lo16|pad8])
#define SL 132            // f32 row stride for logits smem
#define THREADS 256

// Scratch (no allocations allowed)
__device__ __nv_bfloat16 g_A[2048 * SA];   // alpha-GEMM operand, bf16 hi/lo
__device__ float g_c2[256];                // per-component constant (log2 domain)
__device__ float g_stage[M_MODELS * NTILES];

__host__ __device__ __forceinline__ constexpr int tidx(int i, int j) {
    return i * (i + 1) / 2 + j;
}

__device__ __forceinline__ float ex2a(float x) {
    float r; asm("ex2.approx.ftz.f32 %0,%1;" : "=f"(r) : "f"(x)); return r;
}
__device__ __forceinline__ float lg2a(float x) {
    float r; asm("lg2.approx.ftz.f32 %0,%1;" : "=f"(r) : "f"(x)); return r;
}
__device__ __forceinline__ void mma16816(float* c, const unsigned* a, const unsigned* b) {
    asm volatile(
        "mma.sync.aligned.m16n8k16.row.col.f32.bf16.bf16.f32 "
        "{%0,%1,%2,%3}, {%4,%5,%6,%7}, {%8,%9}, {%0,%1,%2,%3};"
        : "+f"(c[0]), "+f"(c[1]), "+f"(c[2]), "+f"(c[3])
        : "r"(a[0]), "r"(a[1]), "r"(a[2]), "r"(a[3]), "r"(b[0]), "r"(b[1]));
}

// ---------------------------------------------------------------------------
// Precompute: 8 blocks x 32 threads; thread = component. Builds the factored
// operand rows A[c*8+i] = [Ls_c[i][0..7], -u_c[i], 0...] as bf16 hi/lo, plus c2.
// ---------------------------------------------------------------------------
__global__ void precompute(const float* __restrict__ phi) {
    const int comp = blockIdx.x * 32 + threadIdx.x;   // 0..255
    const int m = comp >> 3, k = comp & 7;
    const float* pm = phi + m * PHI_DIM;
    const float* Lk = pm + K + K * D + k * TRI;
    const float SCALE = 0.8493218002880191f;          // sqrt(0.5*log2(e))

    float Inv[TRI];
    for (int j = 0; j < D; ++j) {
        Inv[tidx(j, j)] = __fdividef(1.f, Lk[tidx(j, j)]);
        for (int i = j + 1; i < D; ++i) {
            float acc = 0.f;
            for (int p = j; p < i; ++p)
                acc = fmaf(Lk[tidx(i, p)], Inv[tidx(p, j)], acc);
            Inv[tidx(i, j)] = -acc * __fdividef(1.f, Lk[tidx(i, i)]);
        }
    }
    #pragma unroll
    for (int q = 0; q < TRI; ++q) Inv[q] *= SCALE;

    const float* mu = pm + K + k * D;
    float u[D];
    for (int i = 0; i < D; ++i) {
        float s = 0.f;
        for (int j = 0; j <= i; ++j) s = fmaf(Inv[tidx(i, j)], mu[j], s);
        u[i] = s;
    }

    float mx = -CUDART_INF_F;
    for (int q = 0; q < K; ++q) mx = fmaxf(mx, pm[q]);
    float se = 0.f;
    for (int q = 0; q < K; ++q) se += __expf(pm[q] - mx);
    const float log_pi = pm[k] - mx - __logf(se);
    float ld = 0.f;
    for (int i = 0; i < D; ++i) ld += __logf(fmaxf(fabsf(Lk[tidx(i, i)]), 1e-8f));
    g_c2[comp] = (log_pi - 0.5f * (D * 1.8378770664093453f + 2.f * ld))
                 * 1.4426950408889634f;

    for (int i = 0; i < D; ++i) {
        __nv_bfloat16* dst = g_A + (comp * 8 + i) * SA;
        float vals[16];
        #pragma unroll
        for (int s = 0; s < 16; ++s) vals[s] = 0.f;
        for (int j = 0; j <= i; ++j) vals[j] = Inv[tidx(i, j)];
        vals[8] = -u[i];
        #pragma unroll
        for (int s = 0; s < 16; ++s) {
            const __nv_bfloat16 h = __float2bfloat16(vals[s]);
            const __nv_bfloat16 l = __float2bfloat16(vals[s] - __bfloat162float(h));
            dst[s] = h;
            dst[16 + s] = l;
        }
        #pragma unroll
        for (int s = 32; s < 40; ++s) dst[s] = __float2bfloat16(0.f);
    }
}

// ---------------------------------------------------------------------------
// Alpha-GEMM + maha + logsumexp. grid = MBLOCKS*NTILES = 4096, 256 threads.
// bx -> mb = bx>>8 (row block: 16 comps), ntile = bx&255 (128 points).
// ---------------------------------------------------------------------------
__global__ void __launch_bounds__(THREADS) gemm_kernel(const float* __restrict__ X) {
    __shared__ __nv_bfloat16 As[MT * SA];    // 10 KB
    __shared__ __nv_bfloat16 Bs[NTL * SA];   // 10 KB
    __shared__ float slog[16 * SL];          // 8.25 KB
    __shared__ float c2sh[16];
    __shared__ float red[8];

    const int bx = blockIdx.x;
    const int ntile = bx & (NTILES - 1), mb = bx >> 8;
    const int tid = threadIdx.x;
    const int w = tid >> 5, lane = tid & 31;
    const int g = lane >> 2, t = lane & 3;

    // A tile: contiguous copy from global (rows mb*128..+127)
    {
        const uint4* src = reinterpret_cast<const uint4*>(g_A + (size_t)mb * MT * SA);
        uint4* dst = reinterpret_cast<uint4*>(As);
        #pragma unroll
        for (int i = tid; i < MT * SA / 8; i += THREADS) dst[i] = src[i];
    }

    // B tile: thread p builds point features [xh|1 , xl|0]
    if (tid < NTL) {
        const float4* xr = reinterpret_cast<const float4*>(
            X + (size_t)(ntile * NTL + tid) * D);
        const float4 xa = xr[0], xb = xr[1];
        const float z[9] = {xa.x, xa.y, xa.z, xa.w, xb.x, xb.y, xb.z, xb.w, 1.f};
        __nv_bfloat16* br = Bs + tid * SA;
        #pragma unroll
        for (int s = 0; s < 9; ++s) {
            const __nv_bfloat16 h = __float2bfloat16(z[s]);
            const __nv_bfloat16 l = __float2bfloat16(z[s] - __bfloat162float(h));
            br[s] = h;
            br[16 + s] = l;
        }
        #pragma unroll
        for (int s = 9; s < 16; ++s) { br[s] = __float2bfloat16(0.f);
                                       br[16 + s] = __float2bfloat16(0.f); }
        #pragma unroll
        for (int s = 32; s < 40; ++s) br[s] = __float2bfloat16(0.f);
    }
    if (tid < 16) c2sh[tid] = g_c2[mb * 16 + tid];
    __syncthreads();

    // MMA: warp w owns rows w*16..w*16+15 (= comps w*2, w*2+1), all 128 points.
    float c[16][4];
    #pragma unroll
    for (int nt = 0; nt < 16; ++nt)
        #pragma unroll
        for (int f = 0; f < 4; ++f) c[nt][f] = 0.f;

    const int CAs[3] = {0, 0, 16};   // Ah*zh + Ah*zl + Al*zh
    const int CBs[3] = {0, 16, 0};
    #pragma unroll
    for (int ks = 0; ks < 3; ++ks) {
        unsigned a[4];
        const int r0 = w * 16 + g;
        a[0] = *(const unsigned*)&As[r0 * SA + CAs[ks] + 2 * t];
        a[1] = *(const unsigned*)&As[(r0 + 8) * SA + CAs[ks] + 2 * t];
        a[2] = *(const unsigned*)&As[r0 * SA + CAs[ks] + 8 + 2 * t];
        a[3] = *(const unsigned*)&As[(r0 + 8) * SA + CAs[ks] + 8 + 2 * t];
        #pragma unroll
        for (int nt = 0; nt < 16; ++nt) {
            unsigned b[2];
            const int p0 = nt * 8 + g;
            b[0] = *(const unsigned*)&Bs[p0 * SA + CBs[ks] + 2 * t];
            b[1] = *(const unsigned*)&Bs[p0 * SA + CBs[ks] + 8 + 2 * t];
            mma16816(c[nt], a, b);
        }
    }

    // maha = sum over the comp's 8 rows of alpha^2 (xor{4,8,16} over g),
    // then logit = c2 - maha -> slog[comp][point]
    #pragma unroll
    for (int nt = 0; nt < 16; ++nt) {
        #pragma unroll
        for (int h = 0; h < 2; ++h) {
            float s0 = c[nt][2 * h] * c[nt][2 * h];
            float s1 = c[nt][2 * h + 1] * c[nt][2 * h + 1];
            #pragma unroll
            for (int msk = 4; msk <= 16; msk <<= 1) {
                s0 += __shfl_xor_sync(0xffffffffu, s0, msk);
                s1 += __shfl_xor_sync(0xffffffffu, s1, msk);
            }
            if (lane < 4) {
                const int comp = w * 2 + h;
                const float c2v = c2sh[comp];
                slog[comp * SL + nt * 8 + 2 * t] = c2v - s0;
                slog[comp * SL + nt * 8 + 2 * t + 1] = c2v - s1;
            }
        }
    }
    __syncthreads();

    // logsumexp over 8 comps per model; thread = (local model, point)
    {
        const int lm = tid >> 7, p = tid & 127;
        float l[8];
        #pragma unroll
        for (int q = 0; q < 8; ++q) l[q] = slog[(lm * 8 + q) * SL + p];
        float mx01 = fmaxf(l[0], l[1]), mx23 = fmaxf(l[2], l[3]);
        float mx45 = fmaxf(l[4], l[5]), mx67 = fmaxf(l[6], l[7]);
        const float mx = fmaxf(fmaxf(mx01, mx23), fmaxf(mx45, mx67));
        const float s = ((ex2a(l[0] - mx) + ex2a(l[1] - mx)) +
                         (ex2a(l[2] - mx) + ex2a(l[3] - mx))) +
                        ((ex2a(l[4] - mx) + ex2a(l[5] - mx)) +
                         (ex2a(l[6] - mx) + ex2a(l[7] - mx)));
        float v = mx + lg2a(s);
        #pragma unroll
        for (int off = 16; off > 0; off >>= 1)
            v += __shfl_xor_sync(0xffffffffu, v, off);
        if (lane == 0) red[w] = v;
    }
    __syncthreads();
    if (tid < 2) {
        const float sum = (red[4 * tid] + red[4 * tid + 1]) +
                          (red[4 * tid + 2] + red[4 * tid + 3]);
        g_stage[(mb * 2 + tid) * NTILES + ntile] = sum * 0.6931471805599453f;
    }
}

// ---------------------------------------------------------------------------
// Finalize: block = model, 128 threads; deterministic fixed-order sums.
// ---------------------------------------------------------------------------
__global__ void finalize_kernel(const float* __restrict__ phi, float* __restrict__ out) {
    const int m = blockIdx.x;
    const int t = threadIdx.x;
    __shared__ double r1[128];
    __shared__ float r2[128];
    double s = 0.0;
    for (int i = t; i < NTILES; i += 128) s += (double)g_stage[m * NTILES + i];
    float p = 0.f;
    for (int i = t; i < PHI_DIM; i += 128) {
        const float v = phi[m * PHI_DIM + i];
        p = fmaf(v, v, p);
    }
    r1[t] = s; r2[t] = p;
    __syncthreads();
    #pragma unroll
    for (int o = 64; o > 0; o >>= 1) {
        if (t < o) { r1[t] += r1[t + o]; r2[t] += r2[t + o]; }
        __syncthreads();
    }
    if (t == 0) out[m] = (float)(-r1[0] + 0.005 * (double)r2[0]);
}

extern "C" void kernel_launch(void* const* d_in, const int* in_sizes, int n_in,
                              void* d_out, int out_size) {
    const float* phi = (const float*)d_in[0];  // (32, 360)
    const float* X   = (const float*)d_in[1];  // (32768, 8)
    float* out = (float*)d_out;                // (32,)

    precompute<<<8, 32>>>(phi);
    gemm_kernel<<<MBLOCKS * NTILES, THREADS>>>(X);
    finalize_kernel<<<M_MODELS, 128>>>(phi, out);
}